// round 2
// baseline (speedup 1.0000x reference)
#include <cuda_runtime.h>
#include <math.h>

#define Bz    8
#define Nn    2048
#define INC   256
#define OUTC  128
#define EDG   65536
#define ROWS  (Bz*Nn)          // 16384
#define BN_EPS 1e-5f

// ---------------- scratch (static device globals; no runtime alloc) --------
__device__ float d_Wg[INC*OUTC];          // mean-over-heads weight  [256][128]
__device__ float d_Wsd[INC*8];            // [256][8]: j<4 -> a_src proj, j>=4 -> a_dst proj
__device__ float d_g[ROWS*OUTC];          // g = x @ Wg   (8 MB, L2-resident)
__device__ float4 d_ssrc[ROWS];           // per-node per-head src scores
__device__ float4 d_sdst[ROWS];           // per-node per-head dst scores
__device__ unsigned d_bitmap[(Nn*Nn)/32]; // 512 KB dedup bitmap
__device__ int d_counts[Nn];
__device__ int d_rowptr[Nn+1];
__device__ int d_cursor[Nn];
__device__ unsigned char d_keep[EDG];
__device__ int d_col[EDG];
__device__ float d_ssum[OUTC];
__device__ float d_ssumsq[OUTC];
__device__ int d_is64;

// ---------------- edge dtype sniffing ---------------------------------------
// Node ids are in [0, 2048). If buffer is int64 (LE, non-negative), every odd
// 32-bit word is 0. For int32 data, 64 consecutive zero odd-words is ~impossible.
__global__ void k_detect(const unsigned* __restrict__ ei32) {
    if (threadIdx.x == 0 && blockIdx.x == 0) {
        int is64 = 1;
        #pragma unroll 1
        for (int i = 1; i < 128; i += 2)
            if (ei32[i] != 0u) { is64 = 0; break; }
        d_is64 = is64;
    }
}

__device__ __forceinline__ int edge_at(const void* ei, int idx) {
    if (d_is64) return (int)((const long long*)ei)[idx];
    return ((const int*)ei)[idx];
}

// ---------------- reset per-call state --------------------------------------
__global__ void k_reset() {
    int i = blockIdx.x*blockDim.x + threadIdx.x;
    int stride = gridDim.x*blockDim.x;
    for (int j = i; j < (Nn*Nn)/32; j += stride) d_bitmap[j] = 0u;
    if (i < Nn)  { d_counts[i] = 0; d_cursor[i] = 0; }
    if (i < OUTC){ d_ssum[i] = 0.f; d_ssumsq[i] = 0.f; }
}

// ---------------- fold W,a into Wg / Ws / Wd --------------------------------
__global__ void k_weights(const float* __restrict__ W, const float* __restrict__ a) {
    int k = blockIdx.x;          // 0..255
    int c = threadIdx.x;         // 0..127
    __shared__ float red[128];
    float w0 = W[k*512 +       c];
    float w1 = W[k*512 + 128 + c];
    float w2 = W[k*512 + 256 + c];
    float w3 = W[k*512 + 384 + c];
    d_Wg[k*128 + c] = 0.25f*(w0+w1+w2+w3);
    float as = a[c], ad = a[128+c];
    float vals[8] = {w0*as, w1*as, w2*as, w3*as, w0*ad, w1*ad, w2*ad, w3*ad};
    #pragma unroll
    for (int j = 0; j < 8; j++) {
        red[c] = vals[j];
        __syncthreads();
        for (int off = 64; off > 0; off >>= 1) {
            if (c < off) red[c] += red[c+off];
            __syncthreads();
        }
        if (c == 0) d_Wsd[k*8 + j] = red[0];
        __syncthreads();
    }
}

// ---------------- g = x @ Wg : M=16384, N=128, K=256 ------------------------
__global__ void __launch_bounds__(256) k_gemm_g(const float* __restrict__ x) {
    __shared__ __align__(16) float xs[32][64];    // [k][row] transposed
    __shared__ __align__(16) float ws[32][128];   // [k][col]
    int block_row = blockIdx.x * 64;
    int tid = threadIdx.x;
    int tx = tid & 31;          // col group (4 cols)
    int ty = tid >> 5;          // row group (8 rows)
    float acc[8][4];
    #pragma unroll
    for (int r = 0; r < 8; r++)
        #pragma unroll
        for (int q = 0; q < 4; q++) acc[r][q] = 0.f;

    for (int kt = 0; kt < INC; kt += 32) {
        // x tile: 64 rows x 32 k -> transposed into xs
        #pragma unroll
        for (int i = 0; i < 2; i++) {
            int f = tid*2 + i;                // 0..511 float4 slots
            int row = f >> 3;
            int kq  = f & 7;
            float4 v = *(const float4*)(x + (size_t)(block_row+row)*INC + kt + kq*4);
            xs[kq*4+0][row] = v.x;
            xs[kq*4+1][row] = v.y;
            xs[kq*4+2][row] = v.z;
            xs[kq*4+3][row] = v.w;
        }
        // w tile: 32 k x 128 cols
        #pragma unroll
        for (int i = 0; i < 4; i++) {
            int f = i*256 + tid;              // 0..1023 float4 slots
            int k  = f >> 5;
            int c4 = f & 31;
            *(float4*)&ws[k][c4*4] = *(const float4*)(d_Wg + (kt+k)*OUTC + c4*4);
        }
        __syncthreads();
        #pragma unroll
        for (int k = 0; k < 32; k++) {
            float4 xa = *(const float4*)&xs[k][ty*8];
            float4 xb = *(const float4*)&xs[k][ty*8+4];
            float4 w4 = *(const float4*)&ws[k][tx*4];
            float xv[8] = {xa.x,xa.y,xa.z,xa.w,xb.x,xb.y,xb.z,xb.w};
            #pragma unroll
            for (int r = 0; r < 8; r++) {
                acc[r][0] += xv[r]*w4.x;
                acc[r][1] += xv[r]*w4.y;
                acc[r][2] += xv[r]*w4.z;
                acc[r][3] += xv[r]*w4.w;
            }
        }
        __syncthreads();
    }
    #pragma unroll
    for (int r = 0; r < 8; r++) {
        int row = block_row + ty*8 + r;
        *(float4*)(d_g + (size_t)row*OUTC + tx*4) =
            make_float4(acc[r][0], acc[r][1], acc[r][2], acc[r][3]);
    }
}

// ---------------- per-node attention scores: x @ Wsd (16384 x 8) ------------
__global__ void k_scores(const float* __restrict__ x) {
    int warp = (blockIdx.x*blockDim.x + threadIdx.x) >> 5;
    int lane = threadIdx.x & 31;
    if (warp >= ROWS) return;
    const float* xr = x + (size_t)warp*INC;
    float acc[8] = {0,0,0,0,0,0,0,0};
    for (int k = lane; k < INC; k += 32) {
        float xv = xr[k];
        #pragma unroll
        for (int j = 0; j < 8; j++) acc[j] += xv * d_Wsd[k*8+j];
    }
    #pragma unroll
    for (int j = 0; j < 8; j++)
        #pragma unroll
        for (int off = 16; off; off >>= 1)
            acc[j] += __shfl_xor_sync(0xffffffff, acc[j], off);
    if (lane == 0) {
        d_ssrc[warp] = make_float4(acc[0],acc[1],acc[2],acc[3]);
        d_sdst[warp] = make_float4(acc[4],acc[5],acc[6],acc[7]);
    }
}

// ---------------- dedup edges + per-dst degree counts ------------------------
__global__ void k_dedup(const void* __restrict__ ei) {
    int e = blockIdx.x*blockDim.x + threadIdx.x;
    if (e >= EDG) return;
    int s = edge_at(ei, e);
    int d = edge_at(ei, EDG + e);
    unsigned key = (unsigned)d*(unsigned)Nn + (unsigned)s;
    unsigned mask = 1u << (key & 31);
    unsigned old = atomicOr(&d_bitmap[key >> 5], mask);
    if (!(old & mask)) {
        d_keep[e] = 1;
        atomicAdd(&d_counts[d], 1);
    } else {
        d_keep[e] = 0;
    }
}

// ---------------- exclusive scan of counts -> rowptr (N=2048, 1 block) ------
__global__ void k_scan() {
    __shared__ int sm[1024];
    int t = threadIdx.x;
    int a0 = d_counts[2*t], a1 = d_counts[2*t+1];
    int tot = a0 + a1;
    sm[t] = tot;
    __syncthreads();
    for (int off = 1; off < 1024; off <<= 1) {
        int v = (t >= off) ? sm[t-off] : 0;
        __syncthreads();
        sm[t] += v;
        __syncthreads();
    }
    int excl = sm[t] - tot;
    d_rowptr[2*t]   = excl;
    d_rowptr[2*t+1] = excl + a0;
    if (t == 1023) d_rowptr[Nn] = sm[1023];
}

// ---------------- scatter kept edges into CSR col ----------------------------
__global__ void k_scatter(const void* __restrict__ ei) {
    int e = blockIdx.x*blockDim.x + threadIdx.x;
    if (e >= EDG) return;
    if (!d_keep[e]) return;
    int s = edge_at(ei, e);
    int d = edge_at(ei, EDG + e);
    int pos = atomicAdd(&d_cursor[d], 1);
    d_col[d_rowptr[d] + pos] = s;
}

__device__ __forceinline__ float edge_val(float4 ss, float4 sd) {
    float v0 = ss.x + sd.x, v1 = ss.y + sd.y, v2 = ss.z + sd.z, v3 = ss.w + sd.w;
    v0 = v0 > 0.f ? v0 : 0.2f*v0;
    v1 = v1 > 0.f ? v1 : 0.2f*v1;
    v2 = v2 > 0.f ? v2 : 0.2f*v2;
    v3 = v3 > 0.f ? v3 : 0.2f*v3;
    return 0.25f*(v0+v1+v2+v3);
}

// ---------------- per-(b,dst) softmax + weighted gather of g -----------------
#define CAP 1024
__global__ void __launch_bounds__(128) k_agg(float* __restrict__ out) {
    int d   = blockIdx.x;
    int b   = blockIdx.y;
    int tid = threadIdx.x;
    int start = d_rowptr[d], end = d_rowptr[d+1];
    float* o = out + ((size_t)b*Nn + d)*OUTC;
    if (start == end) { o[tid] = 0.f; return; }

    __shared__ float sp[CAP];
    __shared__ int   scol[CAP];
    __shared__ float red[128];

    float4 sd = d_sdst[b*Nn + d];

    // pass 1: row max
    float m = -1e30f;
    for (int j = start + tid; j < end; j += 128) {
        float4 ss = d_ssrc[b*Nn + d_col[j]];
        m = fmaxf(m, edge_val(ss, sd));
    }
    red[tid] = m; __syncthreads();
    for (int off = 64; off; off >>= 1) {
        if (tid < off) red[tid] = fmaxf(red[tid], red[tid+off]);
        __syncthreads();
    }
    m = red[0];

    // pass 2: exp, accumulate unnormalized output (chunked, degree-safe)
    float acc = 0.f, lsum = 0.f;
    for (int base = start; base < end; base += CAP) {
        int cnt = min(CAP, end - base);
        __syncthreads();
        for (int jj = tid; jj < cnt; jj += 128) {
            int s = d_col[base + jj];
            float4 ss = d_ssrc[b*Nn + s];
            float p = __expf(edge_val(ss, sd) - m);
            sp[jj] = p; scol[jj] = s;
            lsum += p;
        }
        __syncthreads();
        const float* gb = d_g + (size_t)b*Nn*OUTC;
        #pragma unroll 4
        for (int jj = 0; jj < cnt; jj++) {
            acc += sp[jj] * gb[(size_t)scol[jj]*OUTC + tid];
        }
    }
    __syncthreads();
    red[tid] = lsum; __syncthreads();
    for (int off = 64; off; off >>= 1) {
        if (tid < off) red[tid] += red[tid+off];
        __syncthreads();
    }
    o[tid] = acc / red[0];
}

// ---------------- BN statistics ---------------------------------------------
__global__ void k_bnstats(const float* __restrict__ out) {
    int c = threadIdx.x;                 // channel
    int r0 = blockIdx.x * (ROWS/128);    // 128 blocks, 128 rows each
    float s = 0.f, s2 = 0.f;
    for (int r = r0; r < r0 + ROWS/128; r++) {
        float v = out[(size_t)r*OUTC + c];
        s += v; s2 += v*v;
    }
    atomicAdd(&d_ssum[c], s);
    atomicAdd(&d_ssumsq[c], s2);
}

// ---------------- BN apply + ELU (in place) ---------------------------------
__global__ void k_final(float* __restrict__ out,
                        const float* __restrict__ gamma,
                        const float* __restrict__ beta) {
    int i = blockIdx.x*blockDim.x + threadIdx.x;
    if (i >= ROWS*OUTC) return;
    int c = i & (OUTC-1);
    const float inv = 1.f/(float)ROWS;
    float mean = d_ssum[c]  * inv;
    float var  = d_ssumsq[c]* inv - mean*mean;
    float v = out[i];
    float y = (v - mean) * rsqrtf(var + BN_EPS) * gamma[c] + beta[c];
    out[i] = y > 0.f ? y : expm1f(y);
}

// ---------------- launch -----------------------------------------------------
extern "C" void kernel_launch(void* const* d_in, const int* in_sizes, int n_in,
                              void* d_out, int out_size) {
    const float* x     = (const float*)d_in[0];
    const void*  ei    = d_in[1];
    const float* W     = (const float*)d_in[2];
    const float* a     = (const float*)d_in[3];
    const float* gamma = (const float*)d_in[4];
    const float* beta  = (const float*)d_in[5];
    float* out = (float*)d_out;

    k_detect <<<1, 32>>>((const unsigned*)ei);
    k_reset  <<<512, 256>>>();
    k_weights<<<INC, 128>>>(W, a);
    k_gemm_g <<<ROWS/64, 256>>>(x);
    k_scores <<<ROWS/8, 256>>>(x);
    k_dedup  <<<EDG/256, 256>>>(ei);
    k_scan   <<<1, 1024>>>();
    k_scatter<<<EDG/256, 256>>>(ei);
    dim3 gagg(Nn, Bz);
    k_agg    <<<gagg, 128>>>(out);
    k_bnstats<<<128, 128>>>(out);
    k_final  <<<(ROWS*OUTC + 255)/256, 256>>>(out, gamma, beta);
}

// round 3
// speedup vs baseline: 1.0565x; 1.0565x over previous
#include <cuda_runtime.h>
#include <cuda_fp16.h>
#include <math.h>

#define Bz    8
#define Nn    2048
#define INC   256
#define OUTC  128
#define EDG   65536
#define ROWS  (Bz*Nn)          // 16384
#define BN_EPS 1e-5f

// ---------------- scratch (static device globals; no runtime alloc) --------
__device__ float d_Wg[INC*OUTC];          // mean-over-heads weight  [256][128]
__device__ float d_Wsd[INC*8];            // [256][8]: j<4 -> a_src proj, j>=4 -> a_dst proj
__device__ __half d_g16[ROWS*OUTC];       // g = x @ Wg in fp16 (4 MB, L2-resident)
__device__ float4 d_ssrc[ROWS];           // per-node per-head src scores
__device__ float4 d_sdst[ROWS];           // per-node per-head dst scores
__device__ unsigned d_bitmap[(Nn*Nn)/32]; // 512 KB dedup bitmap
__device__ int d_counts[Nn];
__device__ int d_rowptr[Nn+1];
__device__ int d_cursor[Nn];
__device__ unsigned char d_keep[EDG];
__device__ int d_col[EDG];
__device__ float d_ssum[OUTC];
__device__ float d_ssumsq[OUTC];
__device__ int d_is64;

// ---------------- reset per-call state + edge dtype sniff --------------------
// Node ids < 2048. If buffer is int64 (LE, non-negative), every odd 32-bit
// word is 0; 64 consecutive zero odd-words from int32 data is ~impossible.
__global__ void k_reset(const unsigned* __restrict__ ei32) {
    int i = blockIdx.x*blockDim.x + threadIdx.x;
    int stride = gridDim.x*blockDim.x;
    for (int j = i; j < (Nn*Nn)/32; j += stride) d_bitmap[j] = 0u;
    if (i < Nn)  { d_counts[i] = 0; d_cursor[i] = 0; }
    if (i < OUTC){ d_ssum[i] = 0.f; d_ssumsq[i] = 0.f; }
    if (i == 0) {
        int is64 = 1;
        #pragma unroll 1
        for (int t = 1; t < 128; t += 2)
            if (ei32[t] != 0u) { is64 = 0; break; }
        d_is64 = is64;
    }
}

__device__ __forceinline__ int edge_at(const void* ei, int idx) {
    if (d_is64) return (int)((const long long*)ei)[idx];
    return ((const int*)ei)[idx];
}

// ---------------- fold W,a into Wg / Wsd -------------------------------------
__global__ void k_weights(const float* __restrict__ W, const float* __restrict__ a) {
    int k = blockIdx.x;          // 0..255
    int c = threadIdx.x;         // 0..127
    __shared__ float red[128];
    float w0 = W[k*512 +       c];
    float w1 = W[k*512 + 128 + c];
    float w2 = W[k*512 + 256 + c];
    float w3 = W[k*512 + 384 + c];
    d_Wg[k*128 + c] = 0.25f*(w0+w1+w2+w3);
    float as = a[c], ad = a[128+c];
    float vals[8] = {w0*as, w1*as, w2*as, w3*as, w0*ad, w1*ad, w2*ad, w3*ad};
    #pragma unroll
    for (int j = 0; j < 8; j++) {
        red[c] = vals[j];
        __syncthreads();
        for (int off = 64; off > 0; off >>= 1) {
            if (c < off) red[c] += red[c+off];
            __syncthreads();
        }
        if (c == 0) d_Wsd[k*8 + j] = red[0];
        __syncthreads();
    }
}

// ---------------- g = x @ Wg : M=16384, N=128, K=256, fp16 output ------------
// 32-row tiles, 128 threads, grid 512 -> ~6 blocks/SM resident.
__global__ void __launch_bounds__(128) k_gemm_g(const float* __restrict__ x) {
    __shared__ __align__(16) float xs[32][36];    // [k][row], padded
    __shared__ __align__(16) float ws[32][128];   // [k][col]
    int block_row = blockIdx.x * 32;
    int tid = threadIdx.x;
    int tx = tid & 31;          // col group (4 cols)
    int ty = tid >> 5;          // row group (8 rows), 0..3
    float acc[8][4];
    #pragma unroll
    for (int r = 0; r < 8; r++)
        #pragma unroll
        for (int q = 0; q < 4; q++) acc[r][q] = 0.f;

    for (int kt = 0; kt < INC; kt += 32) {
        // x tile: 32 rows x 32 k -> transposed
        #pragma unroll
        for (int i = 0; i < 2; i++) {
            int f = tid*2 + i;                // 0..255 float4 slots
            int row = f >> 3;                 // 0..31
            int kq  = f & 7;
            float4 v = *(const float4*)(x + (size_t)(block_row+row)*INC + kt + kq*4);
            xs[kq*4+0][row] = v.x;
            xs[kq*4+1][row] = v.y;
            xs[kq*4+2][row] = v.z;
            xs[kq*4+3][row] = v.w;
        }
        // w tile: 32 k x 128 cols
        #pragma unroll
        for (int i = 0; i < 8; i++) {
            int f = i*128 + tid;              // 0..1023 float4 slots
            int k  = f >> 5;
            int c4 = f & 31;
            *(float4*)&ws[k][c4*4] = *(const float4*)(d_Wg + (kt+k)*OUTC + c4*4);
        }
        __syncthreads();
        #pragma unroll
        for (int k = 0; k < 32; k++) {
            float4 xa = *(const float4*)&xs[k][ty*8];
            float4 xb = *(const float4*)&xs[k][ty*8+4];
            float4 w4 = *(const float4*)&ws[k][tx*4];
            float xv[8] = {xa.x,xa.y,xa.z,xa.w,xb.x,xb.y,xb.z,xb.w};
            #pragma unroll
            for (int r = 0; r < 8; r++) {
                acc[r][0] += xv[r]*w4.x;
                acc[r][1] += xv[r]*w4.y;
                acc[r][2] += xv[r]*w4.z;
                acc[r][3] += xv[r]*w4.w;
            }
        }
        __syncthreads();
    }
    #pragma unroll
    for (int r = 0; r < 8; r++) {
        int row = block_row + ty*8 + r;
        __half2 h0 = __floats2half2_rn(acc[r][0], acc[r][1]);
        __half2 h1 = __floats2half2_rn(acc[r][2], acc[r][3]);
        *(__half2*)&d_g16[(size_t)row*OUTC + tx*4]     = h0;
        *(__half2*)&d_g16[(size_t)row*OUTC + tx*4 + 2] = h1;
    }
}

// ---------------- per-node attention scores: x @ Wsd (16384 x 8) ------------
__global__ void k_scores(const float* __restrict__ x) {
    int warp = (blockIdx.x*blockDim.x + threadIdx.x) >> 5;
    int lane = threadIdx.x & 31;
    if (warp >= ROWS) return;
    const float* xr = x + (size_t)warp*INC;
    float acc[8] = {0,0,0,0,0,0,0,0};
    for (int k = lane; k < INC; k += 32) {
        float xv = xr[k];
        #pragma unroll
        for (int j = 0; j < 8; j++) acc[j] += xv * d_Wsd[k*8+j];
    }
    #pragma unroll
    for (int j = 0; j < 8; j++)
        #pragma unroll
        for (int off = 16; off; off >>= 1)
            acc[j] += __shfl_xor_sync(0xffffffff, acc[j], off);
    if (lane == 0) {
        d_ssrc[warp] = make_float4(acc[0],acc[1],acc[2],acc[3]);
        d_sdst[warp] = make_float4(acc[4],acc[5],acc[6],acc[7]);
    }
}

// ---------------- dedup edges + per-dst degree counts ------------------------
__global__ void k_dedup(const void* __restrict__ ei) {
    int e = blockIdx.x*blockDim.x + threadIdx.x;
    if (e >= EDG) return;
    int s = edge_at(ei, e);
    int d = edge_at(ei, EDG + e);
    unsigned key = (unsigned)d*(unsigned)Nn + (unsigned)s;
    unsigned mask = 1u << (key & 31);
    unsigned old = atomicOr(&d_bitmap[key >> 5], mask);
    if (!(old & mask)) {
        d_keep[e] = 1;
        atomicAdd(&d_counts[d], 1);
    } else {
        d_keep[e] = 0;
    }
}

// ---------------- exclusive scan of counts -> rowptr (N=2048, 1 block) ------
__global__ void k_scan() {
    __shared__ int sm[1024];
    int t = threadIdx.x;
    int a0 = d_counts[2*t], a1 = d_counts[2*t+1];
    int tot = a0 + a1;
    sm[t] = tot;
    __syncthreads();
    for (int off = 1; off < 1024; off <<= 1) {
        int v = (t >= off) ? sm[t-off] : 0;
        __syncthreads();
        sm[t] += v;
        __syncthreads();
    }
    int excl = sm[t] - tot;
    d_rowptr[2*t]   = excl;
    d_rowptr[2*t+1] = excl + a0;
    if (t == 1023) d_rowptr[Nn] = sm[1023];
}

// ---------------- scatter kept edges into CSR col ----------------------------
__global__ void k_scatter(const void* __restrict__ ei) {
    int e = blockIdx.x*blockDim.x + threadIdx.x;
    if (e >= EDG) return;
    if (!d_keep[e]) return;
    int s = edge_at(ei, e);
    int d = edge_at(ei, EDG + e);
    int pos = atomicAdd(&d_cursor[d], 1);
    d_col[d_rowptr[d] + pos] = s;
}

__device__ __forceinline__ float edge_val(float4 ss, float4 sd) {
    float v0 = ss.x + sd.x, v1 = ss.y + sd.y, v2 = ss.z + sd.z, v3 = ss.w + sd.w;
    v0 = v0 > 0.f ? v0 : 0.2f*v0;
    v1 = v1 > 0.f ? v1 : 0.2f*v1;
    v2 = v2 > 0.f ? v2 : 0.2f*v2;
    v3 = v3 > 0.f ? v3 : 0.2f*v3;
    return 0.25f*(v0+v1+v2+v3);
}

// ---------------- per-(b,dst) softmax + weighted gather of g (fp16) ----------
#define CAP 256
__global__ void __launch_bounds__(128) k_agg(float* __restrict__ out) {
    int d   = blockIdx.x;
    int b   = blockIdx.y;
    int tid = threadIdx.x;
    int start = d_rowptr[d], end = d_rowptr[d+1];
    float* o = out + ((size_t)b*Nn + d)*OUTC;
    if (start == end) { o[tid] = 0.f; return; }

    __shared__ float sp[CAP];
    __shared__ int   scol[CAP];
    __shared__ float red[128];

    float4 sd = d_sdst[b*Nn + d];

    // pass 1: row max
    float m = -1e30f;
    for (int j = start + tid; j < end; j += 128) {
        float4 ss = d_ssrc[b*Nn + d_col[j]];
        m = fmaxf(m, edge_val(ss, sd));
    }
    red[tid] = m; __syncthreads();
    for (int off = 64; off; off >>= 1) {
        if (tid < off) red[tid] = fmaxf(red[tid], red[tid+off]);
        __syncthreads();
    }
    m = red[0];

    // pass 2: exp, accumulate unnormalized output (chunked, degree-safe)
    float acc = 0.f, lsum = 0.f;
    const __half* gb = d_g16 + (size_t)b*Nn*OUTC;
    for (int base = start; base < end; base += CAP) {
        int cnt = min(CAP, end - base);
        __syncthreads();
        for (int jj = tid; jj < cnt; jj += 128) {
            int s = d_col[base + jj];
            float4 ss = d_ssrc[b*Nn + s];
            float p = __expf(edge_val(ss, sd) - m);
            sp[jj] = p; scol[jj] = s;
            lsum += p;
        }
        __syncthreads();
        #pragma unroll 8
        for (int jj = 0; jj < cnt; jj++) {
            acc += sp[jj] * __half2float(__ldg(&gb[scol[jj]*OUTC + tid]));
        }
    }
    __syncthreads();
    red[tid] = lsum; __syncthreads();
    for (int off = 64; off; off >>= 1) {
        if (tid < off) red[tid] += red[tid+off];
        __syncthreads();
    }
    o[tid] = acc / red[0];
}

// ---------------- BN statistics ---------------------------------------------
__global__ void k_bnstats(const float* __restrict__ out) {
    int c = threadIdx.x;                 // channel
    int r0 = blockIdx.x * (ROWS/128);    // 128 blocks, 128 rows each
    float s = 0.f, s2 = 0.f;
    for (int r = r0; r < r0 + ROWS/128; r++) {
        float v = out[(size_t)r*OUTC + c];
        s += v; s2 += v*v;
    }
    atomicAdd(&d_ssum[c], s);
    atomicAdd(&d_ssumsq[c], s2);
}

// ---------------- BN apply + ELU (in place) ---------------------------------
__global__ void k_final(float* __restrict__ out,
                        const float* __restrict__ gamma,
                        const float* __restrict__ beta) {
    int i = blockIdx.x*blockDim.x + threadIdx.x;
    if (i >= ROWS*OUTC) return;
    int c = i & (OUTC-1);
    const float inv = 1.f/(float)ROWS;
    float mean = d_ssum[c]  * inv;
    float var  = d_ssumsq[c]* inv - mean*mean;
    float v = out[i];
    float y = (v - mean) * rsqrtf(var + BN_EPS) * gamma[c] + beta[c];
    out[i] = y > 0.f ? y : expm1f(y);
}

// ---------------- launch: fork-join graph ------------------------------------
extern "C" void kernel_launch(void* const* d_in, const int* in_sizes, int n_in,
                              void* d_out, int out_size) {
    const float* x     = (const float*)d_in[0];
    const void*  ei    = d_in[1];
    const float* W     = (const float*)d_in[2];
    const float* a     = (const float*)d_in[3];
    const float* gamma = (const float*)d_in[4];
    const float* beta  = (const float*)d_in[5];
    float* out = (float*)d_out;

    // one-time stream/event setup (host objects only; no device allocation)
    static cudaStream_t s1 = nullptr;
    static cudaEvent_t  e0 = nullptr, e1 = nullptr;
    if (s1 == nullptr) {
        cudaStreamCreateWithFlags(&s1, cudaStreamNonBlocking);
        cudaEventCreateWithFlags(&e0, cudaEventDisableTiming);
        cudaEventCreateWithFlags(&e1, cudaEventDisableTiming);
    }

    // main stream: prep, then big GEMM
    k_reset  <<<512, 256>>>((const unsigned*)ei);
    k_weights<<<INC, 128>>>(W, a);
    cudaEventRecord(e0, 0);
    cudaStreamWaitEvent(s1, e0, 0);
    k_gemm_g <<<ROWS/32, 128>>>(x);

    // side stream: edge pipeline, hidden under the GEMM
    k_scores <<<ROWS/8, 256, 0, s1>>>(x);
    k_dedup  <<<EDG/256, 256, 0, s1>>>(ei);
    k_scan   <<<1, 1024, 0, s1>>>();
    k_scatter<<<EDG/256, 256, 0, s1>>>(ei);
    cudaEventRecord(e1, s1);
    cudaStreamWaitEvent(0, e1, 0);

    // join: aggregation + BN + ELU
    dim3 gagg(Nn, Bz);
    k_agg    <<<gagg, 128>>>(out);
    k_bnstats<<<128, 128>>>(out);
    k_final  <<<(ROWS*OUTC + 255)/256, 256>>>(out, gamma, beta);
}

// round 4
// speedup vs baseline: 1.3651x; 1.2921x over previous
#include <cuda_runtime.h>
#include <cuda_fp16.h>
#include <math.h>

#define Bz    8
#define Nn    2048
#define INC   256
#define OUTC  128
#define EDG   65536
#define ROWS  (Bz*Nn)          // 16384
#define BN_EPS 1e-5f

// ---------------- scratch (static device globals; no runtime alloc) --------
__device__ float d_Wg[INC*OUTC];          // mean-over-heads weight  [256][128]
__device__ float d_Wsd[INC*8];            // [256][8]: j<4 -> a_src proj, j>=4 -> a_dst proj
__device__ __half d_g16[ROWS*OUTC];       // g = x @ Wg in fp16 (4 MB, L2-resident)
__device__ float4 d_ssrc[ROWS];           // per-node per-head src scores
__device__ float4 d_sdst[ROWS];           // per-node per-head dst scores
__device__ unsigned d_bitmap[(Nn*Nn)/32]; // 512 KB dedup bitmap
__device__ int d_counts[Nn];
__device__ int d_rowptr[Nn+1];
__device__ int d_cursor[Nn];
__device__ unsigned char d_keep[EDG];
__device__ int d_col[EDG];
__device__ float d_ssum[OUTC];
__device__ float d_ssumsq[OUTC];
__device__ int d_is64;

// ---------------- reset per-call state + edge dtype sniff --------------------
// Node ids < 2048. If buffer is int64 (LE, non-negative), every odd 32-bit
// word is 0; 64 consecutive zero odd-words from int32 data is ~impossible.
__global__ void k_reset(const unsigned* __restrict__ ei32) {
    int i = blockIdx.x*blockDim.x + threadIdx.x;
    int stride = gridDim.x*blockDim.x;
    for (int j = i; j < (Nn*Nn)/32; j += stride) d_bitmap[j] = 0u;
    if (i < Nn)  { d_counts[i] = 0; d_cursor[i] = 0; }
    if (i < OUTC){ d_ssum[i] = 0.f; d_ssumsq[i] = 0.f; }
    if (i == 0) {
        int is64 = 1;
        #pragma unroll 1
        for (int t = 1; t < 128; t += 2)
            if (ei32[t] != 0u) { is64 = 0; break; }
        d_is64 = is64;
    }
}

__device__ __forceinline__ int edge_at(const void* ei, int idx) {
    if (d_is64) return (int)((const long long*)ei)[idx];
    return ((const int*)ei)[idx];
}

// ---------------- fold W,a into Wg / Wsd (warp-shuffle reductions) -----------
__global__ void k_weights(const float* __restrict__ W, const float* __restrict__ a) {
    int k = blockIdx.x;          // 0..255
    int c = threadIdx.x;         // 0..127
    int lane = c & 31, wid = c >> 5;
    __shared__ float part[4][8];
    float w0 = W[k*512 +       c];
    float w1 = W[k*512 + 128 + c];
    float w2 = W[k*512 + 256 + c];
    float w3 = W[k*512 + 384 + c];
    d_Wg[k*128 + c] = 0.25f*(w0+w1+w2+w3);
    float as = a[c], ad = a[128+c];
    float vals[8] = {w0*as, w1*as, w2*as, w3*as, w0*ad, w1*ad, w2*ad, w3*ad};
    #pragma unroll
    for (int j = 0; j < 8; j++) {
        float v = vals[j];
        #pragma unroll
        for (int off = 16; off; off >>= 1) v += __shfl_xor_sync(0xffffffff, v, off);
        if (lane == 0) part[wid][j] = v;
    }
    __syncthreads();
    if (c < 8) d_Wsd[k*8 + c] = part[0][c] + part[1][c] + part[2][c] + part[3][c];
}

// ---------------- g = x @ Wg : M=16384, N=128, K=256, fp16 output ------------
__global__ void __launch_bounds__(128) k_gemm_g(const float* __restrict__ x) {
    __shared__ __align__(16) float xs[32][36];    // [k][row], padded
    __shared__ __align__(16) float ws[32][128];   // [k][col]
    int block_row = blockIdx.x * 32;
    int tid = threadIdx.x;
    int tx = tid & 31;          // col group (4 cols)
    int ty = tid >> 5;          // row group (8 rows), 0..3
    float acc[8][4];
    #pragma unroll
    for (int r = 0; r < 8; r++)
        #pragma unroll
        for (int q = 0; q < 4; q++) acc[r][q] = 0.f;

    for (int kt = 0; kt < INC; kt += 32) {
        #pragma unroll
        for (int i = 0; i < 2; i++) {
            int f = tid*2 + i;                // 0..255 float4 slots
            int row = f >> 3;                 // 0..31
            int kq  = f & 7;
            float4 v = *(const float4*)(x + (size_t)(block_row+row)*INC + kt + kq*4);
            xs[kq*4+0][row] = v.x;
            xs[kq*4+1][row] = v.y;
            xs[kq*4+2][row] = v.z;
            xs[kq*4+3][row] = v.w;
        }
        #pragma unroll
        for (int i = 0; i < 8; i++) {
            int f = i*128 + tid;              // 0..1023 float4 slots
            int k  = f >> 5;
            int c4 = f & 31;
            *(float4*)&ws[k][c4*4] = *(const float4*)(d_Wg + (kt+k)*OUTC + c4*4);
        }
        __syncthreads();
        #pragma unroll
        for (int k = 0; k < 32; k++) {
            float4 xa = *(const float4*)&xs[k][ty*8];
            float4 xb = *(const float4*)&xs[k][ty*8+4];
            float4 w4 = *(const float4*)&ws[k][tx*4];
            float xv[8] = {xa.x,xa.y,xa.z,xa.w,xb.x,xb.y,xb.z,xb.w};
            #pragma unroll
            for (int r = 0; r < 8; r++) {
                acc[r][0] += xv[r]*w4.x;
                acc[r][1] += xv[r]*w4.y;
                acc[r][2] += xv[r]*w4.z;
                acc[r][3] += xv[r]*w4.w;
            }
        }
        __syncthreads();
    }
    #pragma unroll
    for (int r = 0; r < 8; r++) {
        int row = block_row + ty*8 + r;
        __half2 h0 = __floats2half2_rn(acc[r][0], acc[r][1]);
        __half2 h1 = __floats2half2_rn(acc[r][2], acc[r][3]);
        *(__half2*)&d_g16[(size_t)row*OUTC + tx*4]     = h0;
        *(__half2*)&d_g16[(size_t)row*OUTC + tx*4 + 2] = h1;
    }
}

// ---------------- scores: x @ Wsd via shared Wsd (pad-9, conflict-free) ------
__global__ void __launch_bounds__(256) k_scores(const float* __restrict__ x) {
    __shared__ float sW[INC*9];      // 9 KB, stride 9 => gcd(9,32)=1, no conflicts
    int tid = threadIdx.x;
    for (int i = tid; i < INC*8; i += 256) {
        int k = i >> 3, j = i & 7;
        sW[k*9 + j] = d_Wsd[i];
    }
    __syncthreads();
    int warp = (blockIdx.x*blockDim.x + tid) >> 5;
    int lane = tid & 31;
    if (warp >= ROWS) return;
    const float* xr = x + (size_t)warp*INC;
    float acc[8] = {0,0,0,0,0,0,0,0};
    #pragma unroll
    for (int t = 0; t < 8; t++) {
        float xv = __ldg(&xr[lane + 32*t]);
        int kb = (lane + 32*t)*9;
        #pragma unroll
        for (int j = 0; j < 8; j++) acc[j] += xv * sW[kb + j];
    }
    #pragma unroll
    for (int j = 0; j < 8; j++)
        #pragma unroll
        for (int off = 16; off; off >>= 1)
            acc[j] += __shfl_xor_sync(0xffffffff, acc[j], off);
    if (lane == 0) {
        d_ssrc[warp] = make_float4(acc[0],acc[1],acc[2],acc[3]);
        d_sdst[warp] = make_float4(acc[4],acc[5],acc[6],acc[7]);
    }
}

// ---------------- dedup edges + per-dst degree counts ------------------------
__global__ void k_dedup(const void* __restrict__ ei) {
    int e = blockIdx.x*blockDim.x + threadIdx.x;
    if (e >= EDG) return;
    int s = edge_at(ei, e);
    int d = edge_at(ei, EDG + e);
    unsigned key = (unsigned)d*(unsigned)Nn + (unsigned)s;
    unsigned mask = 1u << (key & 31);
    unsigned old = atomicOr(&d_bitmap[key >> 5], mask);
    if (!(old & mask)) {
        d_keep[e] = 1;
        atomicAdd(&d_counts[d], 1);
    } else {
        d_keep[e] = 0;
    }
}

// ---------------- exclusive scan of counts -> rowptr (N=2048, 1 block) ------
__global__ void k_scan() {
    __shared__ int sm[1024];
    int t = threadIdx.x;
    int a0 = d_counts[2*t], a1 = d_counts[2*t+1];
    int tot = a0 + a1;
    sm[t] = tot;
    __syncthreads();
    for (int off = 1; off < 1024; off <<= 1) {
        int v = (t >= off) ? sm[t-off] : 0;
        __syncthreads();
        sm[t] += v;
        __syncthreads();
    }
    int excl = sm[t] - tot;
    d_rowptr[2*t]   = excl;
    d_rowptr[2*t+1] = excl + a0;
    if (t == 1023) d_rowptr[Nn] = sm[1023];
}

// ---------------- scatter kept edges into CSR col ----------------------------
__global__ void k_scatter(const void* __restrict__ ei) {
    int e = blockIdx.x*blockDim.x + threadIdx.x;
    if (e >= EDG) return;
    if (!d_keep[e]) return;
    int s = edge_at(ei, e);
    int d = edge_at(ei, EDG + e);
    int pos = atomicAdd(&d_cursor[d], 1);
    d_col[d_rowptr[d] + pos] = s;
}

__device__ __forceinline__ float edge_val(float4 ss, float4 sd) {
    float v0 = ss.x + sd.x, v1 = ss.y + sd.y, v2 = ss.z + sd.z, v3 = ss.w + sd.w;
    v0 = v0 > 0.f ? v0 : 0.2f*v0;
    v1 = v1 > 0.f ? v1 : 0.2f*v1;
    v2 = v2 > 0.f ? v2 : 0.2f*v2;
    v3 = v3 > 0.f ? v3 : 0.2f*v3;
    return 0.25f*(v0+v1+v2+v3);
}

// ---------------- per-(b,dst) softmax + gather: half2, 2-edge ILP ------------
#define CAP 256
__global__ void __launch_bounds__(128) k_agg(float* __restrict__ out) {
    int d   = blockIdx.x;
    int b   = blockIdx.y;
    int tid = threadIdx.x;
    int start = d_rowptr[d], end = d_rowptr[d+1];
    float* o = out + ((size_t)b*Nn + d)*OUTC;
    if (start == end) { o[tid] = 0.f; return; }

    __shared__ float sp[CAP];
    __shared__ int   scol[CAP];
    __shared__ float red[128];
    __shared__ float2 spar[128];

    float4 sd = d_sdst[b*Nn + d];

    // pass 1: row max
    float m = -1e30f;
    for (int j = start + tid; j < end; j += 128) {
        float4 ss = d_ssrc[b*Nn + d_col[j]];
        m = fmaxf(m, edge_val(ss, sd));
    }
    red[tid] = m; __syncthreads();
    for (int off = 64; off; off >>= 1) {
        if (tid < off) red[tid] = fmaxf(red[tid], red[tid+off]);
        __syncthreads();
    }
    m = red[0];

    // pass 2: exp + gather. threads = (64 channel-pairs) x (2 edge parities)
    int c2 = tid & 63;
    int u  = tid >> 6;
    float accx = 0.f, accy = 0.f, lsum = 0.f;
    const __half2* gb2 = (const __half2*)(d_g16 + (size_t)b*Nn*OUTC);
    for (int base = start; base < end; base += CAP) {
        int cnt = min(CAP, end - base);
        __syncthreads();
        for (int jj = tid; jj < cnt; jj += 128) {
            int s = d_col[base + jj];
            float4 ss = d_ssrc[b*Nn + s];
            float p = __expf(edge_val(ss, sd) - m);
            sp[jj] = p; scol[jj] = s;
            lsum += p;
        }
        __syncthreads();
        #pragma unroll 4
        for (int jj = u; jj < cnt; jj += 2) {
            float p = sp[jj];
            float2 f = __half22float2(__ldg(&gb2[(size_t)scol[jj]*64 + c2]));
            accx += p * f.x;
            accy += p * f.y;
        }
    }
    __syncthreads();
    red[tid] = lsum; __syncthreads();
    for (int off = 64; off; off >>= 1) {
        if (tid < off) red[tid] += red[tid+off];
        __syncthreads();
    }
    float inv = 1.f / red[0];
    spar[tid] = make_float2(accx, accy);
    __syncthreads();
    if (tid < 64) {
        float2 A = spar[tid], B = spar[tid+64];
        o[2*tid]   = (A.x + B.x) * inv;
        o[2*tid+1] = (A.y + B.y) * inv;
    }
}

// ---------------- BN statistics ---------------------------------------------
__global__ void k_bnstats(const float* __restrict__ out) {
    int c = threadIdx.x;                 // channel
    int r0 = blockIdx.x * (ROWS/128);    // 128 blocks, 128 rows each
    float s = 0.f, s2 = 0.f;
    for (int r = r0; r < r0 + ROWS/128; r++) {
        float v = out[(size_t)r*OUTC + c];
        s += v; s2 += v*v;
    }
    atomicAdd(&d_ssum[c], s);
    atomicAdd(&d_ssumsq[c], s2);
}

// ---------------- BN apply + ELU (in place) ---------------------------------
__global__ void k_final(float* __restrict__ out,
                        const float* __restrict__ gamma,
                        const float* __restrict__ beta) {
    int i = blockIdx.x*blockDim.x + threadIdx.x;
    if (i >= ROWS*OUTC) return;
    int c = i & (OUTC-1);
    const float inv = 1.f/(float)ROWS;
    float mean = d_ssum[c]  * inv;
    float var  = d_ssumsq[c]* inv - mean*mean;
    float v = out[i];
    float y = (v - mean) * rsqrtf(var + BN_EPS) * gamma[c] + beta[c];
    out[i] = y > 0.f ? y : expm1f(y);
}

// ---------------- launch: fork-join graph ------------------------------------
extern "C" void kernel_launch(void* const* d_in, const int* in_sizes, int n_in,
                              void* d_out, int out_size) {
    const float* x     = (const float*)d_in[0];
    const void*  ei    = d_in[1];
    const float* W     = (const float*)d_in[2];
    const float* a     = (const float*)d_in[3];
    const float* gamma = (const float*)d_in[4];
    const float* beta  = (const float*)d_in[5];
    float* out = (float*)d_out;

    static cudaStream_t s1 = nullptr;
    static cudaEvent_t  e0 = nullptr, e1 = nullptr;
    if (s1 == nullptr) {
        cudaStreamCreateWithFlags(&s1, cudaStreamNonBlocking);
        cudaEventCreateWithFlags(&e0, cudaEventDisableTiming);
        cudaEventCreateWithFlags(&e1, cudaEventDisableTiming);
    }

    // main stream: prep, then big GEMM
    k_reset  <<<512, 256>>>((const unsigned*)ei);
    k_weights<<<INC, 128>>>(W, a);
    cudaEventRecord(e0, 0);
    cudaStreamWaitEvent(s1, e0, 0);
    k_gemm_g <<<ROWS/32, 128>>>(x);

    // side stream: edge pipeline, hidden under the GEMM
    k_scores <<<ROWS/8, 256, 0, s1>>>(x);
    k_dedup  <<<EDG/256, 256, 0, s1>>>(ei);
    k_scan   <<<1, 1024, 0, s1>>>();
    k_scatter<<<EDG/256, 256, 0, s1>>>(ei);
    cudaEventRecord(e1, s1);
    cudaStreamWaitEvent(0, e1, 0);

    // join: aggregation + BN + ELU
    dim3 gagg(Nn, Bz);
    k_agg    <<<gagg, 128>>>(out);
    k_bnstats<<<128, 128>>>(out);
    k_final  <<<(ROWS*OUTC + 255)/256, 256>>>(out, gamma, beta);
}

// round 5
// speedup vs baseline: 1.7313x; 1.2683x over previous
#include <cuda_runtime.h>
#include <cuda_fp16.h>
#include <math.h>

#define Bz    8
#define Nn    2048
#define INC   256
#define OUTC  128
#define EDG   65536
#define ROWS  (Bz*Nn)          // 16384
#define BN_EPS 1e-5f

// ---------------- scratch (static device globals; no runtime alloc) --------
__device__ float d_Wg[INC*OUTC];          // mean-over-heads weight  [256][128]
__device__ float d_Wsd[INC*8];            // [256][8]
__device__ __half d_g16[ROWS*OUTC];       // g = x @ Wg in fp16 (4 MB, L2-resident)
__device__ float4 d_ssrc[ROWS];
__device__ float4 d_sdst[ROWS];
__device__ unsigned d_bitmap[(Nn*Nn)/32]; // 512 KB dedup bitmap
__device__ int d_counts[Nn];
__device__ int d_rowptr[Nn+1];
__device__ int d_cursor[Nn];
__device__ unsigned char d_keep[EDG];
__device__ int d_col[EDG];
__device__ float d_ssum[OUTC];
__device__ float d_ssumsq[OUTC];
__device__ int d_is64;

// ---------------- reset + edge dtype sniff ----------------------------------
__global__ void k_reset(const unsigned* __restrict__ ei32) {
    int i = blockIdx.x*blockDim.x + threadIdx.x;
    int stride = gridDim.x*blockDim.x;
    for (int j = i; j < (Nn*Nn)/32; j += stride) d_bitmap[j] = 0u;
    if (i < Nn)  { d_counts[i] = 0; d_cursor[i] = 0; }
    if (i < OUTC){ d_ssum[i] = 0.f; d_ssumsq[i] = 0.f; }
    if (i == 0) {
        int is64 = 1;
        #pragma unroll 1
        for (int t = 1; t < 128; t += 2)
            if (ei32[t] != 0u) { is64 = 0; break; }
        d_is64 = is64;
    }
}

__device__ __forceinline__ int edge_at(const void* ei, int idx) {
    if (d_is64) return (int)((const long long*)ei)[idx];
    return ((const int*)ei)[idx];
}

// ---------------- fold W,a into Wg / Wsd -------------------------------------
__global__ void k_weights(const float* __restrict__ W, const float* __restrict__ a) {
    int k = blockIdx.x;          // 0..255
    int c = threadIdx.x;         // 0..127
    int lane = c & 31, wid = c >> 5;
    __shared__ float part[4][8];
    float w0 = W[k*512 +       c];
    float w1 = W[k*512 + 128 + c];
    float w2 = W[k*512 + 256 + c];
    float w3 = W[k*512 + 384 + c];
    d_Wg[k*128 + c] = 0.25f*(w0+w1+w2+w3);
    float as = a[c], ad = a[128+c];
    float vals[8] = {w0*as, w1*as, w2*as, w3*as, w0*ad, w1*ad, w2*ad, w3*ad};
    #pragma unroll
    for (int j = 0; j < 8; j++) {
        float v = vals[j];
        #pragma unroll
        for (int off = 16; off; off >>= 1) v += __shfl_xor_sync(0xffffffff, v, off);
        if (lane == 0) part[wid][j] = v;
    }
    __syncthreads();
    if (c < 8) d_Wsd[k*8 + c] = part[0][c] + part[1][c] + part[2][c] + part[3][c];
}

// ---------------- g = x @ Wg : 64x128 tile, 128 thr, 8x8/thread --------------
__global__ void __launch_bounds__(128) k_gemm_g(const float* __restrict__ x) {
    __shared__ __align__(16) float xs[32][68];    // [k][row], padded
    __shared__ __align__(16) float ws[32][128];   // [k][col]
    int block_row = blockIdx.x * 64;
    int tid = threadIdx.x;
    int tx = tid & 15;          // col group: 8 cols
    int ty = tid >> 4;          // row group: 8 rows (0..7)
    float acc[8][8];
    #pragma unroll
    for (int r = 0; r < 8; r++)
        #pragma unroll
        for (int q = 0; q < 8; q++) acc[r][q] = 0.f;

    for (int kt = 0; kt < INC; kt += 32) {
        // x tile: 64 rows x 32 k (512 float4), transposed into xs
        #pragma unroll
        for (int i = 0; i < 4; i++) {
            int f = i*128 + tid;              // 0..511
            int row = f >> 3;
            int kq  = f & 7;
            float4 v = *(const float4*)(x + (size_t)(block_row+row)*INC + kt + kq*4);
            xs[kq*4+0][row] = v.x;
            xs[kq*4+1][row] = v.y;
            xs[kq*4+2][row] = v.z;
            xs[kq*4+3][row] = v.w;
        }
        // w tile: 32 k x 128 cols (1024 float4)
        #pragma unroll
        for (int i = 0; i < 8; i++) {
            int f = i*128 + tid;
            int k  = f >> 5;
            int c4 = f & 31;
            *(float4*)&ws[k][c4*4] = *(const float4*)(d_Wg + (kt+k)*OUTC + c4*4);
        }
        __syncthreads();
        #pragma unroll
        for (int k = 0; k < 32; k++) {
            float4 xa = *(const float4*)&xs[k][ty*8];
            float4 xb = *(const float4*)&xs[k][ty*8+4];
            float4 wa = *(const float4*)&ws[k][tx*8];
            float4 wb = *(const float4*)&ws[k][tx*8+4];
            float xv[8] = {xa.x,xa.y,xa.z,xa.w,xb.x,xb.y,xb.z,xb.w};
            float wv[8] = {wa.x,wa.y,wa.z,wa.w,wb.x,wb.y,wb.z,wb.w};
            #pragma unroll
            for (int r = 0; r < 8; r++)
                #pragma unroll
                for (int q = 0; q < 8; q++)
                    acc[r][q] += xv[r]*wv[q];
        }
        __syncthreads();
    }
    #pragma unroll
    for (int r = 0; r < 8; r++) {
        int row = block_row + ty*8 + r;
        __half2 h0 = __floats2half2_rn(acc[r][0], acc[r][1]);
        __half2 h1 = __floats2half2_rn(acc[r][2], acc[r][3]);
        __half2 h2 = __floats2half2_rn(acc[r][4], acc[r][5]);
        __half2 h3 = __floats2half2_rn(acc[r][6], acc[r][7]);
        uint4 u;
        u.x = *(unsigned*)&h0; u.y = *(unsigned*)&h1;
        u.z = *(unsigned*)&h2; u.w = *(unsigned*)&h3;
        *(uint4*)&d_g16[(size_t)row*OUTC + tx*8] = u;
    }
}

// ---------------- scores: x @ Wsd, vectorized shared W (stride 12) -----------
__global__ void __launch_bounds__(256) k_scores(const float* __restrict__ x) {
    __shared__ __align__(16) float sW[INC*12];   // 12 KB; float4-pair per k
    int tid = threadIdx.x;
    for (int i = tid; i < INC*8; i += 256) {
        int k = i >> 3, j = i & 7;
        sW[k*12 + j] = d_Wsd[i];
    }
    __syncthreads();
    int warp = (blockIdx.x*blockDim.x + tid) >> 5;
    int lane = tid & 31;
    if (warp >= ROWS) return;
    const float* xr = x + (size_t)warp*INC;
    float acc[8] = {0,0,0,0,0,0,0,0};
    #pragma unroll
    for (int t = 0; t < 8; t++) {
        int k = lane + 32*t;
        float xv = __ldg(&xr[k]);
        float4 wa = *(const float4*)&sW[k*12];
        float4 wb = *(const float4*)&sW[k*12+4];
        acc[0] += xv*wa.x; acc[1] += xv*wa.y; acc[2] += xv*wa.z; acc[3] += xv*wa.w;
        acc[4] += xv*wb.x; acc[5] += xv*wb.y; acc[6] += xv*wb.z; acc[7] += xv*wb.w;
    }
    #pragma unroll
    for (int j = 0; j < 8; j++)
        #pragma unroll
        for (int off = 16; off; off >>= 1)
            acc[j] += __shfl_xor_sync(0xffffffff, acc[j], off);
    if (lane == 0) {
        d_ssrc[warp] = make_float4(acc[0],acc[1],acc[2],acc[3]);
        d_sdst[warp] = make_float4(acc[4],acc[5],acc[6],acc[7]);
    }
}

// ---------------- dedup edges + per-dst degree counts ------------------------
__global__ void k_dedup(const void* __restrict__ ei) {
    int e = blockIdx.x*blockDim.x + threadIdx.x;
    if (e >= EDG) return;
    int s = edge_at(ei, e);
    int d = edge_at(ei, EDG + e);
    unsigned key = (unsigned)d*(unsigned)Nn + (unsigned)s;
    unsigned mask = 1u << (key & 31);
    unsigned old = atomicOr(&d_bitmap[key >> 5], mask);
    if (!(old & mask)) {
        d_keep[e] = 1;
        atomicAdd(&d_counts[d], 1);
    } else {
        d_keep[e] = 0;
    }
}

// ---------------- exclusive scan of counts -> rowptr -------------------------
__global__ void k_scan() {
    __shared__ int sm[1024];
    int t = threadIdx.x;
    int a0 = d_counts[2*t], a1 = d_counts[2*t+1];
    int tot = a0 + a1;
    sm[t] = tot;
    __syncthreads();
    for (int off = 1; off < 1024; off <<= 1) {
        int v = (t >= off) ? sm[t-off] : 0;
        __syncthreads();
        sm[t] += v;
        __syncthreads();
    }
    int excl = sm[t] - tot;
    d_rowptr[2*t]   = excl;
    d_rowptr[2*t+1] = excl + a0;
    if (t == 1023) d_rowptr[Nn] = sm[1023];
}

// ---------------- scatter kept edges into CSR col ----------------------------
__global__ void k_scatter(const void* __restrict__ ei) {
    int e = blockIdx.x*blockDim.x + threadIdx.x;
    if (e >= EDG) return;
    if (!d_keep[e]) return;
    int s = edge_at(ei, e);
    int d = edge_at(ei, EDG + e);
    int pos = atomicAdd(&d_cursor[d], 1);
    d_col[d_rowptr[d] + pos] = s;
}

__device__ __forceinline__ float edge_val(float4 ss, float4 sd) {
    float v0 = ss.x + sd.x, v1 = ss.y + sd.y, v2 = ss.z + sd.z, v3 = ss.w + sd.w;
    v0 = v0 > 0.f ? v0 : 0.2f*v0;
    v1 = v1 > 0.f ? v1 : 0.2f*v1;
    v2 = v2 > 0.f ? v2 : 0.2f*v2;
    v3 = v3 > 0.f ? v3 : 0.2f*v3;
    return 0.25f*(v0+v1+v2+v3);
}

// ---------------- agg: block per dst, warp per batch, fused BN partials ------
__global__ void __launch_bounds__(256) k_agg(float* __restrict__ out) {
    int d    = blockIdx.x;
    int b    = threadIdx.x >> 5;    // warp = batch
    int lane = threadIdx.x & 31;
    int start = d_rowptr[d], end = d_rowptr[d+1];
    float4* o4 = (float4*)(out + ((size_t)b*Nn + d)*OUTC);  // 32 float4 per row

    if (start == end) { o4[lane] = make_float4(0.f,0.f,0.f,0.f); return; }

    float4 sd = d_sdst[b*Nn + d];

    // warp-local row max
    float m = -1e30f;
    for (int j = start + lane; j < end; j += 32) {
        int s = __ldg(&d_col[j]);
        m = fmaxf(m, edge_val(d_ssrc[b*Nn + s], sd));
    }
    #pragma unroll
    for (int off = 16; off; off >>= 1)
        m = fmaxf(m, __shfl_xor_sync(0xffffffff, m, off));

    // gather: chunks of 32 edges; lane owns one edge per chunk, broadcast p,s
    float a0=0.f, a1=0.f, a2=0.f, a3=0.f, lsum=0.f;
    const __half2* gb2 = (const __half2*)(d_g16 + (size_t)b*Nn*OUTC);
    for (int base = start; base < end; base += 32) {
        int cnt = min(32, end - base);
        int sv = 0; float pv = 0.f;
        if (lane < cnt) {
            sv = __ldg(&d_col[base + lane]);
            pv = __expf(edge_val(d_ssrc[b*Nn + sv], sd) - m);
            lsum += pv;
        }
        for (int jj = 0; jj < cnt; jj++) {
            float p = __shfl_sync(0xffffffff, pv, jj);
            int   s = __shfl_sync(0xffffffff, sv, jj);
            uint2 u = __ldg((const uint2*)(gb2 + (size_t)s*64) + lane);
            __half2 h0 = *(__half2*)&u.x;
            __half2 h1 = *(__half2*)&u.y;
            float2 f0 = __half22float2(h0);
            float2 f1 = __half22float2(h1);
            a0 += p*f0.x; a1 += p*f0.y; a2 += p*f1.x; a3 += p*f1.y;
        }
    }
    #pragma unroll
    for (int off = 16; off; off >>= 1)
        lsum += __shfl_xor_sync(0xffffffff, lsum, off);
    float inv = 1.f / lsum;
    a0 *= inv; a1 *= inv; a2 *= inv; a3 *= inv;
    o4[lane] = make_float4(a0, a1, a2, a3);

    // fused BN partials: sb[warp][channel], then column-sum + global atomic
    __shared__ float sb[8][128];
    __shared__ float sb2[8][128];
    int c0 = lane*4;
    sb [b][c0+0]=a0; sb [b][c0+1]=a1; sb [b][c0+2]=a2; sb [b][c0+3]=a3;
    sb2[b][c0+0]=a0*a0; sb2[b][c0+1]=a1*a1; sb2[b][c0+2]=a2*a2; sb2[b][c0+3]=a3*a3;
    __syncthreads();
    int t = threadIdx.x;
    if (t < 128) {
        float s = 0.f, s2 = 0.f;
        #pragma unroll
        for (int w = 0; w < 8; w++) { s += sb[w][t]; s2 += sb2[w][t]; }
        atomicAdd(&d_ssum[t], s);
        atomicAdd(&d_ssumsq[t], s2);
    }
}

// ---------------- BN apply + ELU (in place) ---------------------------------
__global__ void k_final(float* __restrict__ out,
                        const float* __restrict__ gamma,
                        const float* __restrict__ beta) {
    int i = blockIdx.x*blockDim.x + threadIdx.x;
    if (i >= ROWS*OUTC) return;
    int c = i & (OUTC-1);
    const float inv = 1.f/(float)ROWS;
    float mean = d_ssum[c]  * inv;
    float var  = d_ssumsq[c]* inv - mean*mean;
    float v = out[i];
    float y = (v - mean) * rsqrtf(var + BN_EPS) * gamma[c] + beta[c];
    out[i] = y > 0.f ? y : expm1f(y);
}

// ---------------- launch: fork-join graph ------------------------------------
extern "C" void kernel_launch(void* const* d_in, const int* in_sizes, int n_in,
                              void* d_out, int out_size) {
    const float* x     = (const float*)d_in[0];
    const void*  ei    = d_in[1];
    const float* W     = (const float*)d_in[2];
    const float* a     = (const float*)d_in[3];
    const float* gamma = (const float*)d_in[4];
    const float* beta  = (const float*)d_in[5];
    float* out = (float*)d_out;

    static cudaStream_t s1 = nullptr;
    static cudaEvent_t  e0 = nullptr, e1 = nullptr;
    if (s1 == nullptr) {
        cudaStreamCreateWithFlags(&s1, cudaStreamNonBlocking);
        cudaEventCreateWithFlags(&e0, cudaEventDisableTiming);
        cudaEventCreateWithFlags(&e1, cudaEventDisableTiming);
    }

    // main stream: prep, then big GEMM
    k_reset  <<<512, 256>>>((const unsigned*)ei);
    k_weights<<<INC, 128>>>(W, a);
    cudaEventRecord(e0, 0);
    cudaStreamWaitEvent(s1, e0, 0);
    k_gemm_g <<<ROWS/64, 128>>>(x);

    // side stream: edge pipeline, hidden under the GEMM
    k_scores <<<ROWS/8, 256, 0, s1>>>(x);
    k_dedup  <<<EDG/256, 256, 0, s1>>>(ei);
    k_scan   <<<1, 1024, 0, s1>>>();
    k_scatter<<<EDG/256, 256, 0, s1>>>(ei);
    cudaEventRecord(e1, s1);
    cudaStreamWaitEvent(0, e1, 0);

    // join: aggregation (+BN stats) + BN/ELU
    k_agg    <<<Nn, 256>>>(out);
    k_final  <<<(ROWS*OUTC + 255)/256, 256>>>(out, gamma, beta);
}

// round 6
// speedup vs baseline: 1.8535x; 1.0706x over previous
#include <cuda_runtime.h>
#include <cuda_fp16.h>
#include <math.h>

#define Bz    8
#define Nn    2048
#define INC   256
#define OUTC  128
#define EDG   65536
#define ROWS  (Bz*Nn)          // 16384
#define BN_EPS 1e-5f

// ---------------- scratch (static device globals; no runtime alloc) --------
__device__ float d_Wg[INC*OUTC];          // mean-over-heads weight  [256][128]
__device__ float d_Wsd[INC*8];            // [256][8]
__device__ __half d_g16[ROWS*OUTC];       // g = x @ Wg in fp16 (4 MB, L2-resident)
__device__ float4 d_ssrc[ROWS];
__device__ float4 d_sdst[ROWS];
__device__ unsigned d_bitmap[(Nn*Nn)/32]; // 512 KB dedup bitmap
__device__ int d_counts[Nn];
__device__ int d_rowptr[Nn+1];
__device__ int d_cursor[Nn];
__device__ unsigned char d_keep[EDG];
__device__ int d_col[EDG];
__device__ float d_ssum[OUTC];
__device__ float d_ssumsq[OUTC];
__device__ int d_is64;

// ---------------- reset + edge dtype sniff ----------------------------------
__global__ void k_reset(const unsigned* __restrict__ ei32) {
    int i = blockIdx.x*blockDim.x + threadIdx.x;
    int stride = gridDim.x*blockDim.x;
    for (int j = i; j < (Nn*Nn)/32; j += stride) d_bitmap[j] = 0u;
    if (i < Nn)  { d_counts[i] = 0; d_cursor[i] = 0; }
    if (i < OUTC){ d_ssum[i] = 0.f; d_ssumsq[i] = 0.f; }
    if (i == 0) {
        int is64 = 1;
        #pragma unroll 1
        for (int t = 1; t < 128; t += 2)
            if (ei32[t] != 0u) { is64 = 0; break; }
        d_is64 = is64;
    }
}

__device__ __forceinline__ int edge_at(const void* ei, int idx) {
    if (d_is64) return (int)((const long long*)ei)[idx];
    return ((const int*)ei)[idx];
}

// ---------------- fold W,a into Wg / Wsd -------------------------------------
__global__ void k_weights(const float* __restrict__ W, const float* __restrict__ a) {
    int k = blockIdx.x;          // 0..255
    int c = threadIdx.x;         // 0..127
    int lane = c & 31, wid = c >> 5;
    __shared__ float part[4][8];
    float w0 = W[k*512 +       c];
    float w1 = W[k*512 + 128 + c];
    float w2 = W[k*512 + 256 + c];
    float w3 = W[k*512 + 384 + c];
    d_Wg[k*128 + c] = 0.25f*(w0+w1+w2+w3);
    float as = a[c], ad = a[128+c];
    float vals[8] = {w0*as, w1*as, w2*as, w3*as, w0*ad, w1*ad, w2*ad, w3*ad};
    #pragma unroll
    for (int j = 0; j < 8; j++) {
        float v = vals[j];
        #pragma unroll
        for (int off = 16; off; off >>= 1) v += __shfl_xor_sync(0xffffffff, v, off);
        if (lane == 0) part[wid][j] = v;
    }
    __syncthreads();
    if (c < 8) d_Wsd[k*8 + c] = part[0][c] + part[1][c] + part[2][c] + part[3][c];
}

// ---------------- fused: g = x @ Wg (fp16 out)  AND  scores = x @ Wsd --------
// 64x128 tile, 128 threads, 8x8/thread main GEMM.
// Score ownership: thread t handles row (t>>1), score quad (t&1): even->src, odd->dst.
__global__ void __launch_bounds__(128) k_gemm_g(const float* __restrict__ x) {
    __shared__ __align__(16) float xs[32][68];    // [k][row], padded
    __shared__ __align__(16) float ws[32][128];   // [k][col]
    __shared__ __align__(16) float sWs[32*8];     // Wsd tile [k][8]
    int block_row = blockIdx.x * 64;
    int tid = threadIdx.x;
    int tx = tid & 15;          // col group: 8 cols
    int ty = tid >> 4;          // row group: 8 rows (0..7)
    int srow = tid >> 1;        // score row 0..63
    int sq   = (tid & 1) * 4;   // score quad: 0 = src, 4 = dst
    float acc[8][8];
    float accs0 = 0.f, accs1 = 0.f, accs2 = 0.f, accs3 = 0.f;
    #pragma unroll
    for (int r = 0; r < 8; r++)
        #pragma unroll
        for (int q = 0; q < 8; q++) acc[r][q] = 0.f;

    for (int kt = 0; kt < INC; kt += 32) {
        // x tile: 64 rows x 32 k (512 float4), transposed into xs
        #pragma unroll
        for (int i = 0; i < 4; i++) {
            int f = i*128 + tid;              // 0..511
            int row = f >> 3;
            int kq  = f & 7;
            float4 v = *(const float4*)(x + (size_t)(block_row+row)*INC + kt + kq*4);
            xs[kq*4+0][row] = v.x;
            xs[kq*4+1][row] = v.y;
            xs[kq*4+2][row] = v.z;
            xs[kq*4+3][row] = v.w;
        }
        // w tile: 32 k x 128 cols (1024 float4)
        #pragma unroll
        for (int i = 0; i < 8; i++) {
            int f = i*128 + tid;
            int k  = f >> 5;
            int c4 = f & 31;
            *(float4*)&ws[k][c4*4] = *(const float4*)(d_Wg + (kt+k)*OUTC + c4*4);
        }
        // Wsd tile: 256 floats
        sWs[tid]       = d_Wsd[kt*8 + tid];
        sWs[tid + 128] = d_Wsd[kt*8 + tid + 128];
        __syncthreads();
        #pragma unroll
        for (int k = 0; k < 32; k++) {
            float4 xa = *(const float4*)&xs[k][ty*8];
            float4 xb = *(const float4*)&xs[k][ty*8+4];
            float4 wa = *(const float4*)&ws[k][tx*8];
            float4 wb = *(const float4*)&ws[k][tx*8+4];
            float xv[8] = {xa.x,xa.y,xa.z,xa.w,xb.x,xb.y,xb.z,xb.w};
            float wv[8] = {wa.x,wa.y,wa.z,wa.w,wb.x,wb.y,wb.z,wb.w};
            #pragma unroll
            for (int r = 0; r < 8; r++)
                #pragma unroll
                for (int q = 0; q < 8; q++)
                    acc[r][q] += xv[r]*wv[q];
            // fused score accumulation
            float xvs = xs[k][srow];
            float4 wsd = *(const float4*)&sWs[k*8 + sq];
            accs0 += xvs*wsd.x; accs1 += xvs*wsd.y;
            accs2 += xvs*wsd.z; accs3 += xvs*wsd.w;
        }
        __syncthreads();
    }
    #pragma unroll
    for (int r = 0; r < 8; r++) {
        int row = block_row + ty*8 + r;
        __half2 h0 = __floats2half2_rn(acc[r][0], acc[r][1]);
        __half2 h1 = __floats2half2_rn(acc[r][2], acc[r][3]);
        __half2 h2 = __floats2half2_rn(acc[r][4], acc[r][5]);
        __half2 h3 = __floats2half2_rn(acc[r][6], acc[r][7]);
        uint4 u;
        u.x = *(unsigned*)&h0; u.y = *(unsigned*)&h1;
        u.z = *(unsigned*)&h2; u.w = *(unsigned*)&h3;
        *(uint4*)&d_g16[(size_t)row*OUTC + tx*8] = u;
    }
    // score epilogue: each thread owns its (row, quad)
    float4 sv = make_float4(accs0, accs1, accs2, accs3);
    int grow = block_row + srow;
    if (sq == 0) d_ssrc[grow] = sv;
    else         d_sdst[grow] = sv;
}

// ---------------- dedup edges + per-dst degree counts ------------------------
__global__ void k_dedup(const void* __restrict__ ei) {
    int e = blockIdx.x*blockDim.x + threadIdx.x;
    if (e >= EDG) return;
    int s = edge_at(ei, e);
    int d = edge_at(ei, EDG + e);
    unsigned key = (unsigned)d*(unsigned)Nn + (unsigned)s;
    unsigned mask = 1u << (key & 31);
    unsigned old = atomicOr(&d_bitmap[key >> 5], mask);
    if (!(old & mask)) {
        d_keep[e] = 1;
        atomicAdd(&d_counts[d], 1);
    } else {
        d_keep[e] = 0;
    }
}

// ---------------- exclusive scan of counts -> rowptr -------------------------
__global__ void k_scan() {
    __shared__ int sm[1024];
    int t = threadIdx.x;
    int a0 = d_counts[2*t], a1 = d_counts[2*t+1];
    int tot = a0 + a1;
    sm[t] = tot;
    __syncthreads();
    for (int off = 1; off < 1024; off <<= 1) {
        int v = (t >= off) ? sm[t-off] : 0;
        __syncthreads();
        sm[t] += v;
        __syncthreads();
    }
    int excl = sm[t] - tot;
    d_rowptr[2*t]   = excl;
    d_rowptr[2*t+1] = excl + a0;
    if (t == 1023) d_rowptr[Nn] = sm[1023];
}

// ---------------- scatter kept edges into CSR col ----------------------------
__global__ void k_scatter(const void* __restrict__ ei) {
    int e = blockIdx.x*blockDim.x + threadIdx.x;
    if (e >= EDG) return;
    if (!d_keep[e]) return;
    int s = edge_at(ei, e);
    int d = edge_at(ei, EDG + e);
    int pos = atomicAdd(&d_cursor[d], 1);
    d_col[d_rowptr[d] + pos] = s;
}

__device__ __forceinline__ float edge_val(float4 ss, float4 sd) {
    float v0 = ss.x + sd.x, v1 = ss.y + sd.y, v2 = ss.z + sd.z, v3 = ss.w + sd.w;
    v0 = v0 > 0.f ? v0 : 0.2f*v0;
    v1 = v1 > 0.f ? v1 : 0.2f*v1;
    v2 = v2 > 0.f ? v2 : 0.2f*v2;
    v3 = v3 > 0.f ? v3 : 0.2f*v3;
    return 0.25f*(v0+v1+v2+v3);
}

// ---------------- agg: block/dst, warp/batch, smem-staged chunks, MLP=4 ------
// No max subtraction: scores are bounded (|e| <~ 10), expf exact in fp32,
// softmax is shift-invariant so the result is identical.
#define AGG_CAP 64
__global__ void __launch_bounds__(256) k_agg(float* __restrict__ out) {
    int d    = blockIdx.x;
    int b    = threadIdx.x >> 5;    // warp = batch
    int lane = threadIdx.x & 31;
    int start = d_rowptr[d], end = d_rowptr[d+1];
    float4* o4 = (float4*)(out + ((size_t)b*Nn + d)*OUTC);

    if (start == end) { o4[lane] = make_float4(0.f,0.f,0.f,0.f); return; }

    __shared__ int   scol[AGG_CAP];
    __shared__ float sp[8][AGG_CAP];
    __shared__ float sb[8][128];
    __shared__ float sb2[8][128];

    float4 sd = d_sdst[b*Nn + d];
    float a0=0.f, a1=0.f, a2=0.f, a3=0.f, lsum=0.f;
    const uint2* gb = (const uint2*)(d_g16 + (size_t)b*Nn*OUTC);

    for (int base = start; base < end; base += AGG_CAP) {
        int cnt = min(AGG_CAP, end - base);
        __syncthreads();                       // protect scol reuse
        if (threadIdx.x < cnt) scol[threadIdx.x] = __ldg(&d_col[base + threadIdx.x]);
        __syncthreads();
        for (int jj = lane; jj < cnt; jj += 32) {
            int s = scol[jj];
            float p = __expf(edge_val(d_ssrc[b*Nn + s], sd));
            sp[b][jj] = p;
            lsum += p;
        }
        __syncwarp();
        int jj = 0;
        for (; jj + 4 <= cnt; jj += 4) {
            float p0 = sp[b][jj],   p1 = sp[b][jj+1];
            float p2 = sp[b][jj+2], p3 = sp[b][jj+3];
            int   s0 = scol[jj],    s1 = scol[jj+1];
            int   s2 = scol[jj+2],  s3 = scol[jj+3];
            uint2 u0 = __ldg(gb + (size_t)s0*32 + lane);
            uint2 u1 = __ldg(gb + (size_t)s1*32 + lane);
            uint2 u2 = __ldg(gb + (size_t)s2*32 + lane);
            uint2 u3 = __ldg(gb + (size_t)s3*32 + lane);
            float2 f;
            f = __half22float2(*(__half2*)&u0.x); a0 += p0*f.x; a1 += p0*f.y;
            f = __half22float2(*(__half2*)&u0.y); a2 += p0*f.x; a3 += p0*f.y;
            f = __half22float2(*(__half2*)&u1.x); a0 += p1*f.x; a1 += p1*f.y;
            f = __half22float2(*(__half2*)&u1.y); a2 += p1*f.x; a3 += p1*f.y;
            f = __half22float2(*(__half2*)&u2.x); a0 += p2*f.x; a1 += p2*f.y;
            f = __half22float2(*(__half2*)&u2.y); a2 += p2*f.x; a3 += p2*f.y;
            f = __half22float2(*(__half2*)&u3.x); a0 += p3*f.x; a1 += p3*f.y;
            f = __half22float2(*(__half2*)&u3.y); a2 += p3*f.x; a3 += p3*f.y;
        }
        for (; jj < cnt; jj++) {
            float p = sp[b][jj];
            int   s = scol[jj];
            uint2 u = __ldg(gb + (size_t)s*32 + lane);
            float2 f;
            f = __half22float2(*(__half2*)&u.x); a0 += p*f.x; a1 += p*f.y;
            f = __half22float2(*(__half2*)&u.y); a2 += p*f.x; a3 += p*f.y;
        }
    }
    #pragma unroll
    for (int off = 16; off; off >>= 1)
        lsum += __shfl_xor_sync(0xffffffff, lsum, off);
    float inv = 1.f / lsum;
    a0 *= inv; a1 *= inv; a2 *= inv; a3 *= inv;
    o4[lane] = make_float4(a0, a1, a2, a3);

    // fused BN partials
    int c0 = lane*4;
    sb [b][c0+0]=a0;    sb [b][c0+1]=a1;    sb [b][c0+2]=a2;    sb [b][c0+3]=a3;
    sb2[b][c0+0]=a0*a0; sb2[b][c0+1]=a1*a1; sb2[b][c0+2]=a2*a2; sb2[b][c0+3]=a3*a3;
    __syncthreads();
    int t = threadIdx.x;
    if (t < 128) {
        float s = 0.f, s2 = 0.f;
        #pragma unroll
        for (int w = 0; w < 8; w++) { s += sb[w][t]; s2 += sb2[w][t]; }
        atomicAdd(&d_ssum[t], s);
        atomicAdd(&d_ssumsq[t], s2);
    }
}

// ---------------- BN apply + ELU (in place) ---------------------------------
__global__ void k_final(float* __restrict__ out,
                        const float* __restrict__ gamma,
                        const float* __restrict__ beta) {
    int i = blockIdx.x*blockDim.x + threadIdx.x;
    if (i >= ROWS*OUTC) return;
    int c = i & (OUTC-1);
    const float inv = 1.f/(float)ROWS;
    float mean = d_ssum[c]  * inv;
    float var  = d_ssumsq[c]* inv - mean*mean;
    float v = out[i];
    float y = (v - mean) * rsqrtf(var + BN_EPS) * gamma[c] + beta[c];
    out[i] = y > 0.f ? y : expm1f(y);
}

// ---------------- launch: fork-join graph ------------------------------------
extern "C" void kernel_launch(void* const* d_in, const int* in_sizes, int n_in,
                              void* d_out, int out_size) {
    const float* x     = (const float*)d_in[0];
    const void*  ei    = d_in[1];
    const float* W     = (const float*)d_in[2];
    const float* a     = (const float*)d_in[3];
    const float* gamma = (const float*)d_in[4];
    const float* beta  = (const float*)d_in[5];
    float* out = (float*)d_out;

    static cudaStream_t s1 = nullptr;
    static cudaEvent_t  e0 = nullptr, e1 = nullptr;
    if (s1 == nullptr) {
        cudaStreamCreateWithFlags(&s1, cudaStreamNonBlocking);
        cudaEventCreateWithFlags(&e0, cudaEventDisableTiming);
        cudaEventCreateWithFlags(&e1, cudaEventDisableTiming);
    }

    // fork side stream at t=0
    cudaEventRecord(e0, 0);
    cudaStreamWaitEvent(s1, e0, 0);

    // main stream: weights -> fused GEMM+scores
    k_weights<<<INC, 128>>>(W, a);
    k_gemm_g <<<ROWS/64, 128>>>(x);

    // side stream: edge pipeline (independent of weights/GEMM)
    k_reset  <<<512, 256, 0, s1>>>((const unsigned*)ei);
    k_dedup  <<<EDG/256, 256, 0, s1>>>(ei);
    k_scan   <<<1, 1024, 0, s1>>>();
    k_scatter<<<EDG/256, 256, 0, s1>>>(ei);
    cudaEventRecord(e1, s1);
    cudaStreamWaitEvent(0, e1, 0);

    // join: aggregation (+BN stats) + BN/ELU
    k_agg    <<<Nn, 256>>>(out);
    k_final  <<<(ROWS*OUTC + 255)/256, 256>>>(out, gamma, beta);
}